// round 6
// baseline (speedup 1.0000x reference)
#include <cuda_runtime.h>
#include <math_constants.h>

#define IMG_H 1024
#define IMG_W 1024
#define IMG   (IMG_H * IMG_W)
#define NIMG  16
#define NF    32            // z: [0..15]=pred(sigmoid(logits)), [16..31]=gt(target)
#define NIT   5             // skeleton iterations, fully fused
#define OUTC  104           // emitted cols per warp (128-col window, 12-col halo)
#define HALO  12
#define XT    10            // ceil(1024/104)
#define R     64            // emitted rows per warp
#define NWARP 4
#define FINF  CUDART_INF_F

__device__ double g_acc[NF];   // [0..15]=tp per image, [16..31]=ts per image

__device__ __forceinline__ float sigmoidf(float x) { return 1.f / (1.f + __expf(-x)); }
__device__ __forceinline__ float4 vmin3(float4 a, float4 b, float4 c) {
    return make_float4(fminf(a.x, fminf(b.x, c.x)), fminf(a.y, fminf(b.y, c.y)),
                       fminf(a.z, fminf(b.z, c.z)), fminf(a.w, fminf(b.w, c.w)));
}
__device__ __forceinline__ float4 vmax3(float4 a, float4 b, float4 c) {
    return make_float4(fmaxf(a.x, fmaxf(b.x, c.x)), fmaxf(a.y, fmaxf(b.y, c.y)),
                       fmaxf(a.z, fmaxf(b.z, c.z)), fmaxf(a.w, fmaxf(b.w, c.w)));
}
__device__ __forceinline__ float4 hmin(float4 v) {
    float l = __shfl_up_sync(0xffffffffu, v.w, 1);
    float r = __shfl_down_sync(0xffffffffu, v.x, 1);
    return make_float4(fminf(l,   fminf(v.x, v.y)),
                       fminf(v.x, fminf(v.y, v.z)),
                       fminf(v.y, fminf(v.z, v.w)),
                       fminf(v.z, fminf(v.w, r)));
}
__device__ __forceinline__ float4 hmax(float4 v) {
    float l = __shfl_up_sync(0xffffffffu, v.w, 1);
    float r = __shfl_down_sync(0xffffffffu, v.x, 1);
    return make_float4(fmaxf(l,   fmaxf(v.x, v.y)),
                       fmaxf(v.x, fmaxf(v.y, v.z)),
                       fmaxf(v.y, fmaxf(v.z, v.w)),
                       fmaxf(v.z, fmaxf(v.w, r)));
}
__device__ __forceinline__ float4 upd(float4 x, float4 op, float4 er) {
    return make_float4(__saturatef(x.x - (op.x - er.x)),
                       __saturatef(x.y - (op.y - er.y)),
                       __saturatef(x.z - (op.z - er.z)),
                       __saturatef(x.w - (op.w - er.w)));
}

__global__ void zero_kernel() { if (threadIdx.x < NF) g_acc[threadIdx.x] = 0.0; }

// ---------------------------------------------------------------------------
// Single fused pass: x0 = sigmoid(logits) | (float)target, 5 soft-skeleton
// iterations as a lag-9 rolling register pipeline, reduction at emission.
// Per warp: 128-col float4 window, emits inner 104 cols x R rows.
// ---------------------------------------------------------------------------
__global__ void __launch_bounds__(NWARP * 32)
skel_kernel(const float* __restrict__ logits, const int* __restrict__ target)
{
    const int lane = threadIdx.x & 31;
    const int warp = threadIdx.x >> 5;
    const int z    = blockIdx.z;
    const int c0   = blockIdx.x * OUTC - HALO + lane * 4;
    const int row0 = (blockIdx.y * NWARP + warp) * R;

    const bool v0 = (unsigned)c0       < IMG_W;
    const bool v1 = (unsigned)(c0 + 1) < IMG_W;
    const bool v2 = (unsigned)(c0 + 2) < IMG_W;
    const bool v3 = (unsigned)(c0 + 3) < IMG_W;
    const bool allv = (c0 >= 0) && (c0 + 3 < IMG_W);
    const bool emitOK = (lane >= 3) && (lane <= 28) && (unsigned)c0 < IMG_W;
    const bool isPred = (z < NIMG);

    const int img = isPred ? z : z - NIMG;
    const float* __restrict__ lg = logits + (size_t)img * IMG;
    const int*   __restrict__ tg = target + (size_t)img * IMG;

    const float4 P4 = make_float4( FINF,  FINF,  FINF,  FINF);
    const float4 N4 = make_float4(-FINF, -FINF, -FINF, -FINF);

    auto ld1 = [&](long long idx, bool v) -> float {
        if (!v) return FINF;
        return isPred ? sigmoidf(__ldg(lg + idx)) : (float)__ldg(tg + idx);
    };
    auto ldrow = [&](int r) -> float4 {
        if ((unsigned)r >= IMG_H) return P4;
        long long rb = (long long)r * IMG_W;
        if (allv) {
            if (isPred) {
                float4 l = __ldg((const float4*)(lg + rb + c0));
                return make_float4(sigmoidf(l.x), sigmoidf(l.y),
                                   sigmoidf(l.z), sigmoidf(l.w));
            }
            int4 t = __ldg((const int4*)(tg + rb + c0));
            return make_float4((float)t.x, (float)t.y, (float)t.z, (float)t.w);
        }
        return make_float4(ld1(rb + c0, v0), ld1(rb + c0 + 1, v1),
                           ld1(rb + c0 + 2, v2), ld1(rb + c0 + 3, v3));
    };
    auto cmaskN = [&](float4 e) -> float4 {   // OOB image col -> -inf (dilation pad)
        if (allv) return e;
        return make_float4(v0 ? e.x : -FINF, v1 ? e.y : -FINF,
                           v2 ? e.z : -FINF, v3 ? e.w : -FINF);
    };
    auto cmaskP = [&](float4 e) -> float4 {   // OOB image col -> +inf (erosion pad)
        if (allv) return e;
        return make_float4(v0 ? e.x : FINF, v1 ? e.y : FINF,
                           v2 ? e.z : FINF, v3 ? e.w : FINF);
    };

    // Rolling pipelines: stage j (0..4): inputs ua/ub (rows r-1, r), eroded ea/eb
    // (rows r-2, r-1) where r = k - 2j at loop step k.
    float4 ua[NIT], ub[NIT], ea[NIT], eb[NIT];
    #pragma unroll
    for (int j = 0; j < NIT; ++j) { ua[j] = P4; ub[j] = P4; ea[j] = N4; eb[j] = N4; }
    ua[0] = ldrow(row0 - 10);
    ub[0] = ldrow(row0 - 9);

    float accum = 0.f;

    #pragma unroll 2
    for (int k = row0 - 9; k <= row0 + R + 8; ++k) {
        float4 uc = ldrow(k + 1);          // stage-0 input row k+1
        #pragma unroll
        for (int j = 0; j < NIT; ++j) {
            const int er_row = k - 2 * j;
            // erosion at row er_row
            float4 ec = hmin(vmin3(ua[j], ub[j], uc));
            ec = ((unsigned)er_row < IMG_H) ? cmaskN(ec) : N4;
            // dilation + update at row er_row - 1
            float4 un = upd(ua[j], hmax(vmax3(ea[j], eb[j], ec)), eb[j]);
            // shift this stage's pipelines
            ua[j] = ub[j]; ub[j] = uc;
            ea[j] = eb[j]; eb[j] = ec;
            if (j < NIT - 1) {
                un = ((unsigned)(er_row - 1) < IMG_H) ? cmaskP(un) : P4;
                uc = un;                   // feed next stage
            } else if (k >= row0 + 9 && emitOK) {
                // emission: row k-9, cols c0..c0+3 (all valid)
                long long ob = (long long)(k - 9) * IMG_W + c0;
                float4 w;
                if (isPred) {              // tp: skel_pred * target
                    int4 t = __ldg((const int4*)(tg + ob));
                    w = make_float4((float)t.x, (float)t.y, (float)t.z, (float)t.w);
                } else {                   // ts: skel_gt * sigmoid(logits)
                    float4 l = __ldg((const float4*)(lg + ob));
                    w = make_float4(sigmoidf(l.x), sigmoidf(l.y),
                                    sigmoidf(l.z), sigmoidf(l.w));
                }
                accum += un.x * w.x + un.y * w.y + un.z * w.z + un.w * w.w;
            }
        }
    }

    // block reduction -> per-image accumulator
    #pragma unroll
    for (int o = 16; o > 0; o >>= 1)
        accum += __shfl_down_sync(0xffffffffu, accum, o);
    __shared__ float sacc[NWARP];
    if (lane == 0) sacc[warp] = accum;
    __syncthreads();
    if (threadIdx.x == 0) {
        float t = 0.f;
        #pragma unroll
        for (int i = 0; i < NWARP; ++i) t += sacc[i];
        atomicAdd(&g_acc[z], (double)t);
    }
}

// ---------------------------------------------------------------------------
__global__ void final_kernel(float* __restrict__ out)
{
    const int t = threadIdx.x;
    float v = 0.f;
    if (t < NIMG) {
        double tp = g_acc[t], ts = g_acc[NIMG + t];
        double num = 2.0 * tp * ts;
        double den = tp + ts;
        double c = (den > 0.0) ? (num + 1e-6) / (den + 1e-6) : 1.0;
        c = fmin(fmax(c, 0.0), 1.0);
        v = (float)(1.0 - c);
    }
    for (int o = 16; o > 0; o >>= 1) v += __shfl_down_sync(0xffffffffu, v, o);
    if (t == 0) out[0] = v / (float)NIMG;
}

// ---------------------------------------------------------------------------
extern "C" void kernel_launch(void* const* d_in, const int* in_sizes, int n_in,
                              void* d_out, int out_size)
{
    const float* logits = (const float*)d_in[0];
    const int*   target = (const int*)d_in[1];
    float*       out    = (float*)d_out;

    zero_kernel<<<1, 32>>>();
    dim3 grid(XT, IMG_H / (R * NWARP), NF);   // 10 x 4 x 32 = 1280 blocks
    skel_kernel<<<grid, NWARP * 32>>>(logits, target);
    final_kernel<<<1, 32>>>(out);
}

// round 7
// speedup vs baseline: 1.2074x; 1.2074x over previous
#include <cuda_runtime.h>
#include <math_constants.h>

#define IMG_H 1024
#define IMG_W 1024
#define IMG   (IMG_H * IMG_W)
#define NIMG  16
#define NF    32            // [0..15]=pred(sigmoid(logits)), [16..31]=gt(target)
#define OUTC  120           // output cols per warp (128-col window, 4-col halo/side)
#define XT    9             // ceil(1024/120)
#define R     16            // output rows per warp
#define NWARP 4
#define FINF  CUDART_INF_F

__device__ float  g_bufA[(size_t)NF * IMG];   // 128 MB scratch
__device__ float  g_bufB[(size_t)NF * IMG];   // 128 MB scratch
__device__ double g_acc[NF];                  // [0..15]=tp, [16..31]=ts

__device__ __forceinline__ float sigmoidf(float x) { return 1.f / (1.f + __expf(-x)); }
__device__ __forceinline__ float4 vmin3(float4 a, float4 b, float4 c) {
    return make_float4(fminf(a.x, fminf(b.x, c.x)), fminf(a.y, fminf(b.y, c.y)),
                       fminf(a.z, fminf(b.z, c.z)), fminf(a.w, fminf(b.w, c.w)));
}
__device__ __forceinline__ float4 vmax3(float4 a, float4 b, float4 c) {
    return make_float4(fmaxf(a.x, fmaxf(b.x, c.x)), fmaxf(a.y, fmaxf(b.y, c.y)),
                       fmaxf(a.z, fmaxf(b.z, c.z)), fmaxf(a.w, fmaxf(b.w, c.w)));
}
__device__ __forceinline__ float4 vmin2(float4 a, float4 m) {
    return make_float4(fminf(a.x, m.x), fminf(a.y, m.y),
                       fminf(a.z, m.z), fminf(a.w, m.w));
}
__device__ __forceinline__ float4 vmax2(float4 a, float4 m) {
    return make_float4(fmaxf(a.x, m.x), fmaxf(a.y, m.y),
                       fmaxf(a.z, m.z), fmaxf(a.w, m.w));
}
__device__ __forceinline__ float4 hmin(float4 v) {
    float l = __shfl_up_sync(0xffffffffu, v.w, 1);
    float r = __shfl_down_sync(0xffffffffu, v.x, 1);
    return make_float4(fminf(l,   fminf(v.x, v.y)),
                       fminf(v.x, fminf(v.y, v.z)),
                       fminf(v.y, fminf(v.z, v.w)),
                       fminf(v.z, fminf(v.w, r)));
}
__device__ __forceinline__ float4 hmax(float4 v) {
    float l = __shfl_up_sync(0xffffffffu, v.w, 1);
    float r = __shfl_down_sync(0xffffffffu, v.x, 1);
    return make_float4(fmaxf(l,   fmaxf(v.x, v.y)),
                       fmaxf(v.x, fmaxf(v.y, v.z)),
                       fmaxf(v.y, fmaxf(v.z, v.w)),
                       fmaxf(v.z, fmaxf(v.w, r)));
}
__device__ __forceinline__ float4 upd(float4 x, float4 op, float4 er) {
    return make_float4(__saturatef(x.x - (op.x - er.x)),
                       __saturatef(x.y - (op.y - er.y)),
                       __saturatef(x.z - (op.z - er.z)),
                       __saturatef(x.w - (op.w - er.w)));
}

// ---------------------------------------------------------------------------
// MODE 0: x = sigmoid(logits)/(float)target; 2 skeleton iterations; store.
// MODE 1: load buffer; 2 skeleton iterations; store.
// MODE 2: load buffer; 1 skeleton iteration; accumulate tp/ts (no store).
// Column masking via loop-invariant +-inf vectors (fmin/fmax), no predicates.
// ---------------------------------------------------------------------------
template<int MODE>
__global__ void __launch_bounds__(NWARP * 32, 10)
skel_kernel(const float* __restrict__ src,
            const float* __restrict__ logits,
            const int*   __restrict__ target,
            float*       __restrict__ dst)
{
    const int lane = threadIdx.x & 31;
    const int warp = threadIdx.x >> 5;
    const int z    = blockIdx.z;
    const int c0   = blockIdx.x * OUTC - 4 + lane * 4;
    const int row0 = (blockIdx.y * NWARP + warp) * R;
    const bool v0 = (unsigned)c0       < IMG_W;
    const bool v1 = (unsigned)(c0 + 1) < IMG_W;
    const bool v2 = (unsigned)(c0 + 2) < IMG_W;
    const bool v3 = (unsigned)(c0 + 3) < IMG_W;
    const bool allv = (c0 >= 0) && (c0 + 3 < IMG_W);
    // mask vectors: mN -> invalid col becomes -inf via fmin; mP -> +inf via fmax
    const float4 mN = make_float4(v0 ?  FINF : -FINF, v1 ?  FINF : -FINF,
                                  v2 ?  FINF : -FINF, v3 ?  FINF : -FINF);
    const float4 mP = make_float4(v0 ? -FINF :  FINF, v1 ? -FINF :  FINF,
                                  v2 ? -FINF :  FINF, v3 ? -FINF :  FINF);

    if (MODE == 0 && blockIdx.x == 0 && blockIdx.y == 0 && blockIdx.z == 0 &&
        threadIdx.x < NF)
        g_acc[threadIdx.x] = 0.0;   // stream-ordered before MODE 2 atomics

    const int img = (z < NIMG) ? z : z - NIMG;
    const float* __restrict__ lg = logits + (size_t)img * IMG;
    const int*   __restrict__ tg = target + (size_t)img * IMG;
    const float* __restrict__ sp = (MODE != 0) ? src + (size_t)z * IMG : nullptr;
    float* __restrict__ dp = (MODE != 2) ? dst + (size_t)z * IMG : nullptr;

    const float4 P4 = make_float4( FINF,  FINF,  FINF,  FINF);
    const float4 N4 = make_float4(-FINF, -FINF, -FINF, -FINF);

    auto ld1 = [&](long long idx, bool v) -> float {
        if (!v) return FINF;
        if (MODE == 0)
            return (z < NIMG) ? sigmoidf(__ldg(lg + idx)) : (float)__ldg(tg + idx);
        return __ldg(sp + idx);
    };
    auto ldrow = [&](int r) -> float4 {
        if ((unsigned)r >= IMG_H) return P4;
        long long rb = (long long)r * IMG_W;
        if (allv) {
            if (MODE == 0) {
                if (z < NIMG) {
                    float4 l = __ldg((const float4*)(lg + rb + c0));
                    return make_float4(sigmoidf(l.x), sigmoidf(l.y),
                                       sigmoidf(l.z), sigmoidf(l.w));
                }
                int4 t = __ldg((const int4*)(tg + rb + c0));
                return make_float4((float)t.x, (float)t.y, (float)t.z, (float)t.w);
            }
            return __ldg((const float4*)(sp + rb + c0));
        }
        return make_float4(ld1(rb + c0, v0), ld1(rb + c0 + 1, v1),
                           ld1(rb + c0 + 2, v2), ld1(rb + c0 + 3, v3));
    };
    const bool emitLane = (lane >= 1) && (lane <= 30);
    float accum = 0.f;

    if (MODE != 2) {
        // ---- two fused skeleton iterations (lag-4 rolling pipeline) ----
        float4 xa = ldrow(row0 - 4), xb = ldrow(row0 - 3);
        float4 e1a = N4, e1b = N4, pa = P4, pb = P4, qa = N4, qb = N4;
        #pragma unroll 2
        for (int k = row0 - 3; k <= row0 + R + 2; ++k) {
            float4 xc = ldrow(k + 1);
            // er1 row k
            float4 e1 = ((unsigned)k < IMG_H)
                      ? vmin2(hmin(vmin3(xa, xb, xc)), mN) : N4;
            // x' row k-1
            float4 op1 = hmax(vmax3(e1a, e1b, e1));
            float4 xp  = ((unsigned)(k - 1) < IMG_H)
                       ? vmax2(upd(xa, op1, e1b), mP) : P4;
            // er2 row k-2
            float4 e2 = ((unsigned)(k - 2) < IMG_H)
                      ? vmin2(hmin(vmin3(pa, pb, xp)), mN) : N4;
            // emit x'' row k-3
            if (k >= row0 + 3) {
                float4 op2 = hmax(vmax3(qa, qb, e2));
                float4 nx  = upd(pa, op2, qb);
                if (emitLane) {
                    long long ob = (long long)(k - 3) * IMG_W + c0;
                    if (c0 + 3 < IMG_W) {
                        *(float4*)(dp + ob) = nx;
                    } else {
                        if (v0) dp[ob]     = nx.x;
                        if (v1) dp[ob + 1] = nx.y;
                        if (v2) dp[ob + 2] = nx.z;
                        if (v3) dp[ob + 3] = nx.w;
                    }
                }
            }
            qa = qb; qb = e2; pa = pb; pb = xp;
            e1a = e1b; e1b = e1; xa = xb; xb = xc;
        }
    } else {
        // ---- final skeleton iteration + reduction ----
        float4 xa = ldrow(row0 - 2), xb = ldrow(row0 - 1);
        float4 e1a = N4, e1b = N4;
        #pragma unroll 2
        for (int k = row0 - 1; k <= row0 + R; ++k) {
            float4 xc = ldrow(k + 1);
            float4 e1 = ((unsigned)k < IMG_H)
                      ? vmin2(hmin(vmin3(xa, xb, xc)), mN) : N4;
            if (k >= row0 + 1) {
                float4 op = hmax(vmax3(e1a, e1b, e1));
                float4 nx = upd(xa, op, e1b);          // row k-1, saturated finite
                if (emitLane) {
                    long long ob = (long long)(k - 1) * IMG_W + c0;
                    float4 w = make_float4(0.f, 0.f, 0.f, 0.f);
                    if (z < NIMG) {                    // tp: skel_pred * target
                        if (allv) {
                            int4 t = __ldg((const int4*)(tg + ob));
                            w = make_float4((float)t.x, (float)t.y, (float)t.z, (float)t.w);
                        } else {
                            if (v0) w.x = (float)__ldg(tg + ob);
                            if (v1) w.y = (float)__ldg(tg + ob + 1);
                            if (v2) w.z = (float)__ldg(tg + ob + 2);
                            if (v3) w.w = (float)__ldg(tg + ob + 3);
                        }
                    } else {                           // ts: skel_gt * sigmoid(logits)
                        if (allv) {
                            float4 l = __ldg((const float4*)(lg + ob));
                            w = make_float4(sigmoidf(l.x), sigmoidf(l.y),
                                            sigmoidf(l.z), sigmoidf(l.w));
                        } else {
                            if (v0) w.x = sigmoidf(__ldg(lg + ob));
                            if (v1) w.y = sigmoidf(__ldg(lg + ob + 1));
                            if (v2) w.z = sigmoidf(__ldg(lg + ob + 2));
                            if (v3) w.w = sigmoidf(__ldg(lg + ob + 3));
                        }
                    }
                    accum += nx.x * w.x + nx.y * w.y + nx.z * w.z + nx.w * w.w;
                }
            }
            e1a = e1b; e1b = e1; xa = xb; xb = xc;
        }
        #pragma unroll
        for (int o = 16; o > 0; o >>= 1)
            accum += __shfl_down_sync(0xffffffffu, accum, o);
        __shared__ float sacc[NWARP];
        if (lane == 0) sacc[warp] = accum;
        __syncthreads();
        if (threadIdx.x == 0) {
            float t = 0.f;
            #pragma unroll
            for (int i = 0; i < NWARP; ++i) t += sacc[i];
            atomicAdd(&g_acc[z], (double)t);
        }
    }
}

// ---------------------------------------------------------------------------
__global__ void final_kernel(float* __restrict__ out)
{
    const int t = threadIdx.x;
    float v = 0.f;
    if (t < NIMG) {
        double tp = g_acc[t], ts = g_acc[NIMG + t];
        double num = 2.0 * tp * ts;
        double den = tp + ts;
        double c = (den > 0.0) ? (num + 1e-6) / (den + 1e-6) : 1.0;
        c = fmin(fmax(c, 0.0), 1.0);
        v = (float)(1.0 - c);
    }
    for (int o = 16; o > 0; o >>= 1) v += __shfl_down_sync(0xffffffffu, v, o);
    if (t == 0) out[0] = v / (float)NIMG;
}

// ---------------------------------------------------------------------------
extern "C" void kernel_launch(void* const* d_in, const int* in_sizes, int n_in,
                              void* d_out, int out_size)
{
    const float* logits = (const float*)d_in[0];
    const int*   target = (const int*)d_in[1];
    float*       out    = (float*)d_out;

    float *A = nullptr, *B = nullptr;
    cudaGetSymbolAddress((void**)&A, g_bufA);
    cudaGetSymbolAddress((void**)&B, g_bufB);

    dim3 grid(XT, IMG_H / (R * NWARP), NF);   // 9 x 16 x 32 = 4608 blocks
    const int blk = NWARP * 32;

    skel_kernel<0><<<grid, blk>>>(nullptr, logits, target, A);  // sigmoid + iters 1-2
    skel_kernel<1><<<grid, blk>>>(A, nullptr, nullptr, B);      // iters 3-4
    skel_kernel<2><<<grid, blk>>>(B, logits, target, nullptr);  // iter 5 + reduce
    final_kernel<<<1, 32>>>(out);
}